// round 11
// baseline (speedup 1.0000x reference)
#include <cuda_runtime.h>
#include <cuda_fp16.h>

#define HH 2048
#define WW 2048
#define HWN (HH*WW)
#define W4 (WW/4)
#define HW4 (HWN/4)
#define NCTA 148
#define NTHR 512
#define MAXR 14
#define SUB 8

// dyn smem: s_im uint2[7168]=57344B, s_rm uint2[7168]=57344B, lut 1KB, cdf 1KB, hist/cdfp 8KB
#define SMEM_BYTES (MAXR*512*8*2 + 1024 + 1024 + 256*SUB*4)

__device__ double g_sums[4];      // 0:recon 1:r_smooth(x255, int-exact) 2:ismooth 3:eq
__device__ unsigned int g_hist[256];
__device__ int g_minbits;
__device__ int g_maxbits;
__device__ unsigned int g_bar;

__global__ void k_zero() {
    int t = threadIdx.x;
    if (t < 256) g_hist[t] = 0u;
    if (t < 4) g_sums[t] = 0.0;
    if (t == 0) { g_minbits = 0x7F800000; g_maxbits = 0; g_bar = 0u; }
}

__device__ __forceinline__ int q8(float x) {
    return __float2int_rd(__saturatef(x) * 255.0f);
}
__device__ __forceinline__ int grayi(int q0, int q1, int q2) {
    return (19595 * q0 + 38470 * q1 + 7471 * q2 + 32768) >> 16;
}
__device__ __forceinline__ unsigned packh2(float a, float b) {
    __half2 h = __floats2half2_rn(a, b);
    return *reinterpret_cast<unsigned*>(&h);
}
__device__ __forceinline__ float2 unpackh2(unsigned u) {
    __half2 h = *reinterpret_cast<__half2*>(&u);
    return __half22float2(h);
}

// Grid barrier; residency: 1 CTA/SM (125KB smem), NCTA=148 <= SM count.
__device__ __forceinline__ void gridbar(unsigned target) {
    __syncthreads();
    if (threadIdx.x == 0) {
        __threadfence();
        atomicAdd(&g_bar, 1u);
        while (*(volatile unsigned*)&g_bar < target) { }
    }
    __syncthreads();
    __threadfence();
}

// interp with paired cdf: p[k] = (cdf[k], cdf[k+1]); p[255] = (cdf255, cdf255)
__device__ __forceinline__ float interp1p(float x, float gmin, float scale, const float2* cdfp) {
    float u = fmaxf((x - gmin) * scale, 0.0f);
    int k = min((int)u, 255);
    float2 p = cdfp[k];
    return fmaf(p.y - p.x, u - (float)k, p.x);   // slope 0 at k=255 -> returns cdf[255]
}

struct Row { float4 a0, a1, a2, b0, b1, b2, lv; };

__device__ __forceinline__ Row load_row(const float4* __restrict__ in,
                                        const float4* __restrict__ Rp,
                                        const float4* __restrict__ Lp, int idx) {
    Row r;
    r.a0 = __ldcs(&in[idx]); r.a1 = __ldcs(&in[idx + HW4]); r.a2 = __ldcs(&in[idx + 2 * HW4]);
    r.b0 = __ldcs(&Rp[idx]); r.b1 = __ldcs(&Rp[idx + HW4]); r.b2 = __ldcs(&Rp[idx + 2 * HW4]);
    r.lv = __ldcs(&Lp[idx]);
    return r;
}

__global__ __launch_bounds__(NTHR, 1) void kmain(const float4* __restrict__ in,
                                                 const float4* __restrict__ Rp,
                                                 const float4* __restrict__ Lp,
                                                 float* __restrict__ out) {
    extern __shared__ char sm[];
    uint2*    s_im  = (uint2*)sm;                          // fp16x4 im_max
    uint2*    s_rm  = (uint2*)(sm + MAXR*512*8);           // fp16x4 r_max
    float*    s_lut = (float*)(sm + MAXR*512*16);
    float*    s_cdf = s_lut + 256;
    unsigned* s_h   = (unsigned*)(s_cdf + 256);            // phase 2; reused as cdfp in phase 3
    float2*   s_cdfp = (float2*)s_h;
    __shared__ double redd[3][16];
    __shared__ float  redf[2][16];

    const int tid = threadIdx.x;
    const int cta = blockIdx.x;

    // slab: CTAs 0..123 -> 14 rows, 124..147 -> 13 rows (124*14 + 24*13 = 2048)
    int nr, r0;
    if (cta < 124) { nr = 14; r0 = cta * 14; }
    else           { nr = 13; r0 = 1736 + (cta - 124) * 13; }

    for (int i = tid; i < 256; i += NTHR)
        s_lut[i] = __expf((float)i * (-10.0f / 255.0f));
    __syncthreads();

    // ---------------- Phase 1: depth-2 software-pipelined streaming ----------------
    const int col = tid;
    int gPx, gPy, gPz, gPw;
    float4 lP;
    if (r0 == 0) {
        gPx = gPy = gPz = gPw = 0;
        lP = make_float4(0.f, 0.f, 0.f, 0.f);
    } else {
        int idx = (r0 - 1) * W4 + col;
        float4 b0 = __ldcs(&Rp[idx]), b1 = __ldcs(&Rp[idx + HW4]), b2 = __ldcs(&Rp[idx + 2 * HW4]);
        gPx = grayi(q8(b0.x), q8(b1.x), q8(b2.x));
        gPy = grayi(q8(b0.y), q8(b1.y), q8(b2.y));
        gPz = grayi(q8(b0.z), q8(b1.z), q8(b2.z));
        gPw = grayi(q8(b0.w), q8(b1.w), q8(b2.w));
        lP = __ldcs(&Lp[idx]);
    }

    float sRec = 0.f, sIs = 0.f;
    int   sRsI = 0;
    float vmin = 3.0f, vmax = -1.0f;

    const int base = r0 * W4 + col;
    Row cur = load_row(in, Rp, Lp, base);
    Row nxt = load_row(in, Rp, Lp, base + W4);

    auto body = [&](const Row& r, int rr) {
        sRec +=
            fabsf(r.b0.x * r.lv.x - r.a0.x) + fabsf(r.b0.y * r.lv.y - r.a0.y) +
            fabsf(r.b0.z * r.lv.z - r.a0.z) + fabsf(r.b0.w * r.lv.w - r.a0.w) +
            fabsf(r.b1.x * r.lv.x - r.a1.x) + fabsf(r.b1.y * r.lv.y - r.a1.y) +
            fabsf(r.b1.z * r.lv.z - r.a1.z) + fabsf(r.b1.w * r.lv.w - r.a1.w) +
            fabsf(r.b2.x * r.lv.x - r.a2.x) + fabsf(r.b2.y * r.lv.y - r.a2.y) +
            fabsf(r.b2.z * r.lv.z - r.a2.z) + fabsf(r.b2.w * r.lv.w - r.a2.w);

        float imx = fmaxf(r.a0.x, fmaxf(r.a1.x, r.a2.x));
        float imy = fmaxf(r.a0.y, fmaxf(r.a1.y, r.a2.y));
        float imz = fmaxf(r.a0.z, fmaxf(r.a1.z, r.a2.z));
        float imw = fmaxf(r.a0.w, fmaxf(r.a1.w, r.a2.w));
        float rmx = fmaxf(r.b0.x, fmaxf(r.b1.x, r.b2.x));
        float rmy = fmaxf(r.b0.y, fmaxf(r.b1.y, r.b2.y));
        float rmz = fmaxf(r.b0.z, fmaxf(r.b1.z, r.b2.z));
        float rmw = fmaxf(r.b0.w, fmaxf(r.b1.w, r.b2.w));

        int li = rr * 512 + col;
        s_im[li] = make_uint2(packh2(imx, imy), packh2(imz, imw));
        s_rm[li] = make_uint2(packh2(rmx, rmy), packh2(rmz, rmw));

        vmin = fminf(vmin, fminf(fminf(imx, imy), fminf(imz, imw)));
        vmax = fmaxf(vmax, fmaxf(fmaxf(imx, imy), fmaxf(imz, imw)));

        int gx = grayi(q8(r.b0.x), q8(r.b1.x), q8(r.b2.x));
        int gy = grayi(q8(r.b0.y), q8(r.b1.y), q8(r.b2.y));
        int gz = grayi(q8(r.b0.z), q8(r.b1.z), q8(r.b2.z));
        int gw = grayi(q8(r.b0.w), q8(r.b1.w), q8(r.b2.w));

        int dgx = abs(gx - gPx), dgy = abs(gy - gPy);
        int dgz = abs(gz - gPz), dgw = abs(gw - gPw);
        sRsI += dgx + dgy + dgz + dgw + 2 * (gx + gy + gz + gw);

        sIs += fabsf(r.lv.x - lP.x) * s_lut[dgx] + 2.0f * fabsf(r.lv.x) * s_lut[gx]
             + fabsf(r.lv.y - lP.y) * s_lut[dgy] + 2.0f * fabsf(r.lv.y) * s_lut[gy]
             + fabsf(r.lv.z - lP.z) * s_lut[dgz] + 2.0f * fabsf(r.lv.z) * s_lut[gz]
             + fabsf(r.lv.w - lP.w) * s_lut[dgw] + 2.0f * fabsf(r.lv.w) * s_lut[gw];

        gPx = gx; gPy = gy; gPz = gz; gPw = gw;
        lP = r.lv;
    };

    #pragma unroll 1
    for (int rr = 0; rr < nr - 2; rr++) {
        Row nn = load_row(in, Rp, Lp, base + (rr + 2) * W4);
        body(cur, rr);
        cur = nxt;
        nxt = nn;
    }
    body(cur, nr - 2);
    body(nxt, nr - 1);

    if (r0 + nr == HH) {   // bottom padded edge
        sRsI += gPx + gPy + gPz + gPw;
        sIs  += fabsf(lP.x) * s_lut[gPx] + fabsf(lP.y) * s_lut[gPy]
              + fabsf(lP.z) * s_lut[gPz] + fabsf(lP.w) * s_lut[gPw];
    }

    // block reduce (16 warps)
    double dRec = (double)sRec, dIs = (double)sIs;
    int    iRs = sRsI;
    const unsigned m = 0xffffffffu;
    for (int o = 16; o; o >>= 1) {
        dRec += __shfl_down_sync(m, dRec, o);
        dIs  += __shfl_down_sync(m, dIs,  o);
        iRs  += __shfl_down_sync(m, iRs,  o);
        vmin = fminf(vmin, __shfl_down_sync(m, vmin, o));
        vmax = fmaxf(vmax, __shfl_down_sync(m, vmax, o));
    }
    int lane = tid & 31, wid = tid >> 5;
    if (lane == 0) {
        redd[0][wid] = dRec; redd[1][wid] = (double)iRs; redd[2][wid] = dIs;
        redf[0][wid] = vmin; redf[1][wid] = vmax;
    }
    __syncthreads();
    if (wid == 0) {
        double dRs;
        dRec = (lane < 16) ? redd[0][lane] : 0.0;
        dRs  = (lane < 16) ? redd[1][lane] : 0.0;
        dIs  = (lane < 16) ? redd[2][lane] : 0.0;
        vmin = (lane < 16) ? redf[0][lane] : 3.0f;
        vmax = (lane < 16) ? redf[1][lane] : -1.0f;
        for (int o = 8; o; o >>= 1) {
            dRec += __shfl_down_sync(m, dRec, o);
            dRs  += __shfl_down_sync(m, dRs,  o);
            dIs  += __shfl_down_sync(m, dIs,  o);
            vmin = fminf(vmin, __shfl_down_sync(m, vmin, o));
            vmax = fmaxf(vmax, __shfl_down_sync(m, vmax, o));
        }
        if (lane == 0) {
            atomicAdd(&g_sums[0], dRec);
            atomicAdd(&g_sums[1], dRs);
            atomicAdd(&g_sums[2], dIs);
            atomicMin(&g_minbits, __float_as_int(vmin));
            atomicMax(&g_maxbits, __float_as_int(vmax));
        }
    }

    gridbar(NCTA);

    // ---------------- Phase 2: histogram from smem ----------------
    const float gmin = __int_as_float(__ldcg(&g_minbits));
    const float gmax = __int_as_float(__ldcg(&g_maxbits));
    const float scale = 256.0f / (gmax - gmin);

    for (int i = tid; i < 256 * SUB; i += NTHR) s_h[i] = 0u;
    __syncthreads();
    const unsigned sub = tid & (SUB - 1);
    const int nelem = nr * 512;
    for (int i = tid; i < nelem; i += NTHR) {
        uint2 u = s_im[i];
        float2 v0 = unpackh2(u.x);
        float2 v1 = unpackh2(u.y);
        int k0 = min(255, (int)fmaxf((v0.x - gmin) * scale, 0.0f));
        int k1 = min(255, (int)fmaxf((v0.y - gmin) * scale, 0.0f));
        int k2 = min(255, (int)fmaxf((v1.x - gmin) * scale, 0.0f));
        int k3 = min(255, (int)fmaxf((v1.y - gmin) * scale, 0.0f));
        atomicAdd(&s_h[k0 * SUB + sub], 1u);
        atomicAdd(&s_h[k1 * SUB + sub], 1u);
        atomicAdd(&s_h[k2 * SUB + sub], 1u);
        atomicAdd(&s_h[k3 * SUB + sub], 1u);
    }
    __syncthreads();
    if (tid < 256) {
        unsigned s = 0;
        #pragma unroll
        for (int j = 0; j < SUB; j++) s += s_h[tid * SUB + j];
        if (s) atomicAdd(&g_hist[tid], s);
    }

    gridbar(2 * NCTA);

    // ---------------- Phase 3: cdf + paired interp + eq-sum ----------------
    if (tid < 256) s_cdf[tid] = (float)__ldcg(&g_hist[tid]);   // total 2^22: exact in fp32
    __syncthreads();
    for (int off = 1; off < 256; off <<= 1) {
        float t = 0.0f;
        if (tid < 256 && tid >= off) t = s_cdf[tid - off];
        __syncthreads();
        if (tid < 256) s_cdf[tid] += t;
        __syncthreads();
    }
    float norm = s_cdf[255];
    __syncthreads();
    if (tid < 256) s_cdf[tid] = s_cdf[tid] / norm;
    __syncthreads();
    if (tid < 256) {
        float c0 = s_cdf[tid];
        float c1 = (tid < 255) ? s_cdf[tid + 1] : c0;
        s_cdfp[tid] = make_float2(c0, c1);
    }
    __syncthreads();

    float sEq = 0.f;
    for (int i = tid; i < nelem; i += NTHR) {
        uint2 u = s_im[i];
        uint2 ru = s_rm[i];
        float2 v0 = unpackh2(u.x), v1 = unpackh2(u.y);
        float2 r0f = unpackh2(ru.x), r1f = unpackh2(ru.y);
        sEq += fabsf(r0f.x - interp1p(v0.x, gmin, scale, s_cdfp))
             + fabsf(r0f.y - interp1p(v0.y, gmin, scale, s_cdfp))
             + fabsf(r1f.x - interp1p(v1.x, gmin, scale, s_cdfp))
             + fabsf(r1f.y - interp1p(v1.y, gmin, scale, s_cdfp));
    }
    double dEq = (double)sEq;
    for (int o = 16; o; o >>= 1) dEq += __shfl_down_sync(m, dEq, o);
    if (lane == 0) redd[0][wid] = dEq;
    __syncthreads();
    if (wid == 0) {
        dEq = (lane < 16) ? redd[0][lane] : 0.0;
        for (int o = 8; o; o >>= 1) dEq += __shfl_down_sync(m, dEq, o);
        if (lane == 0) atomicAdd(&g_sums[3], dEq);
    }

    gridbar(3 * NCTA);

    // ---------------- Final combine ----------------
    if (cta == 0 && tid == 0) {
        double recon = __ldcg(&g_sums[0]) / (3.0 * (double)HWN);
        double denom = 2.0 * (double)(HH + 1) * (double)(WW + 2);
        double rs = __ldcg(&g_sums[1]) / (255.0 * denom);
        double is = __ldcg(&g_sums[2]) / denom;
        double eq = __ldcg(&g_sums[3]) / (double)HWN;
        out[0] = (float)(recon + 0.1 * is + 0.1 * eq + 0.01 * rs);
    }
}

extern "C" void kernel_launch(void* const* d_in, const int* in_sizes, int n_in,
                              void* d_out, int out_size) {
    const float4* in = (const float4*)d_in[0];
    const float4* Rp = (const float4*)d_in[1];
    const float4* Lp = (const float4*)d_in[2];
    (void)in_sizes; (void)n_in; (void)out_size;

    cudaFuncSetAttribute(kmain, cudaFuncAttributeMaxDynamicSharedMemorySize, SMEM_BYTES);

    k_zero<<<1, 256>>>();
    kmain<<<NCTA, NTHR, SMEM_BYTES>>>(in, Rp, Lp, (float*)d_out);
}

// round 14
// speedup vs baseline: 1.0131x; 1.0131x over previous
#include <cuda_runtime.h>
#include <cuda_fp16.h>

#define HH 2048
#define WW 2048
#define HWN (HH*WW)
#define W4 (WW/4)
#define HW4 (HWN/4)
#define NCTA 148
#define NTHR 512
#define MAXR 14
#define FB 2048            // fine fixed bins over [0,1]

// dyn smem: s_im 57344B + s_rm 57344B + s_ch 1KB + s_cdf 1KB + s_fh 8KB = 124928B
#define SMEM_BYTES (MAXR*512*8*2 + 1024 + 1024 + FB*4)

__device__ double g_sums[4];      // 0:recon 1:r_smooth(x255, int-exact) 2:ismooth 3:eq
__device__ unsigned int g_fhist[FB];
__device__ int g_minbits;
__device__ int g_maxbits;
__device__ unsigned int g_bar;

__global__ void k_zero() {
    int t = threadIdx.x;
    for (int i = t; i < FB; i += 256) g_fhist[i] = 0u;
    if (t < 4) g_sums[t] = 0.0;
    if (t == 0) { g_minbits = 0x7F800000; g_maxbits = 0; g_bar = 0u; }
}

__device__ __forceinline__ int q8(float x) {
    return __float2int_rd(__saturatef(x) * 255.0f);
}
__device__ __forceinline__ int grayi(int q0, int q1, int q2) {
    return (19595 * q0 + 38470 * q1 + 7471 * q2 + 32768) >> 16;
}
__device__ __forceinline__ unsigned packh2(float a, float b) {
    __half2 h = __floats2half2_rn(a, b);
    return *reinterpret_cast<unsigned*>(&h);
}
__device__ __forceinline__ float2 unpackh2(unsigned u) {
    __half2 h = *reinterpret_cast<__half2*>(&u);
    return __half22float2(h);
}

// Grid barrier; residency: 1 CTA/SM (122KB smem), NCTA=148 <= SM count.
__device__ __forceinline__ void gridbar(unsigned target) {
    __syncthreads();
    if (threadIdx.x == 0) {
        __threadfence();
        atomicAdd(&g_bar, 1u);
        while (*(volatile unsigned*)&g_bar < target) { }
    }
    __syncthreads();
    __threadfence();
}

// interp with paired cdf: p[k] = (cdf[k], cdf[k+1]); p[255] = (cdf255, cdf255)
__device__ __forceinline__ float interp1p(float x, float gmin, float scale, const float2* cdfp) {
    float u = fmaxf((x - gmin) * scale, 0.0f);
    int k = min((int)u, 255);
    float2 p = cdfp[k];
    return fmaf(p.y - p.x, u - (float)k, p.x);
}

__global__ __launch_bounds__(NTHR, 1) void kmain(const float4* __restrict__ in,
                                                 const float4* __restrict__ Rp,
                                                 const float4* __restrict__ Lp,
                                                 float* __restrict__ out) {
    extern __shared__ char sm[];
    uint2*    s_im  = (uint2*)sm;                          // fp16x4 im_max
    uint2*    s_rm  = (uint2*)(sm + MAXR*512*8);           // fp16x4 r_max
    unsigned* s_ch  = (unsigned*)(sm + MAXR*512*16);       // phase1: lut / phase3: coarse hist
    float*    s_lut = (float*)s_ch;                        // same 1KB region (phase 1 only)
    float*    s_cdf = (float*)(sm + MAXR*512*16 + 1024);
    unsigned* s_fh  = (unsigned*)(sm + MAXR*512*16 + 2048);  // fine hist; reused as cdfp
    float2*   s_cdfp = (float2*)s_fh;
    __shared__ double redd[3][16];
    __shared__ float  redf[2][16];

    const int tid = threadIdx.x;
    const int cta = blockIdx.x;

    // slab: CTAs 0..123 -> 14 rows, 124..147 -> 13 rows (124*14 + 24*13 = 2048)
    int nr, r0;
    if (cta < 124) { nr = 14; r0 = cta * 14; }
    else           { nr = 13; r0 = 1736 + (cta - 124) * 13; }

    for (int i = tid; i < 256; i += NTHR)
        s_lut[i] = __expf((float)i * (-10.0f / 255.0f));
    for (int i = tid; i < FB; i += NTHR) s_fh[i] = 0u;
    __syncthreads();

    // ---------------- Phase 1: fused streaming pass + fine histogram ----------------
    const int col = tid;
    int gPx, gPy, gPz, gPw;
    float4 lP;
    if (r0 == 0) {
        gPx = gPy = gPz = gPw = 0;
        lP = make_float4(0.f, 0.f, 0.f, 0.f);
    } else {
        int idx = (r0 - 1) * W4 + col;
        float4 b0 = __ldcs(&Rp[idx]), b1 = __ldcs(&Rp[idx + HW4]), b2 = __ldcs(&Rp[idx + 2 * HW4]);
        gPx = grayi(q8(b0.x), q8(b1.x), q8(b2.x));
        gPy = grayi(q8(b0.y), q8(b1.y), q8(b2.y));
        gPz = grayi(q8(b0.z), q8(b1.z), q8(b2.z));
        gPw = grayi(q8(b0.w), q8(b1.w), q8(b2.w));
        lP = __ldcs(&Lp[idx]);
    }

    float sRec = 0.f, sIs = 0.f;
    int   sRsI = 0;
    float vmin = 3.0f, vmax = -1.0f;

    int idx = r0 * W4 + col;
    float4 a0 = __ldcs(&in[idx]), a1 = __ldcs(&in[idx + HW4]), a2 = __ldcs(&in[idx + 2 * HW4]);
    float4 b0 = __ldcs(&Rp[idx]), b1 = __ldcs(&Rp[idx + HW4]), b2 = __ldcs(&Rp[idx + 2 * HW4]);
    float4 lv = __ldcs(&Lp[idx]);

    auto body = [&](int rr) {
        sRec +=
            fabsf(b0.x * lv.x - a0.x) + fabsf(b0.y * lv.y - a0.y) +
            fabsf(b0.z * lv.z - a0.z) + fabsf(b0.w * lv.w - a0.w) +
            fabsf(b1.x * lv.x - a1.x) + fabsf(b1.y * lv.y - a1.y) +
            fabsf(b1.z * lv.z - a1.z) + fabsf(b1.w * lv.w - a1.w) +
            fabsf(b2.x * lv.x - a2.x) + fabsf(b2.y * lv.y - a2.y) +
            fabsf(b2.z * lv.z - a2.z) + fabsf(b2.w * lv.w - a2.w);

        float imx = fmaxf(a0.x, fmaxf(a1.x, a2.x));
        float imy = fmaxf(a0.y, fmaxf(a1.y, a2.y));
        float imz = fmaxf(a0.z, fmaxf(a1.z, a2.z));
        float imw = fmaxf(a0.w, fmaxf(a1.w, a2.w));
        float rmx = fmaxf(b0.x, fmaxf(b1.x, b2.x));
        float rmy = fmaxf(b0.y, fmaxf(b1.y, b2.y));
        float rmz = fmaxf(b0.z, fmaxf(b1.z, b2.z));
        float rmw = fmaxf(b0.w, fmaxf(b1.w, b2.w));

        int li = rr * 512 + col;
        s_im[li] = make_uint2(packh2(imx, imy), packh2(imz, imw));
        s_rm[li] = make_uint2(packh2(rmx, rmy), packh2(rmz, rmw));

        vmin = fminf(vmin, fminf(fminf(imx, imy), fminf(imz, imw)));
        vmax = fmaxf(vmax, fmaxf(fmaxf(imx, imy), fmaxf(imz, imw)));

        // fine fixed-bin histogram (exact fp32 values, no min/max dependency)
        atomicAdd(&s_fh[min(FB - 1, (int)(imx * (float)FB))], 1u);
        atomicAdd(&s_fh[min(FB - 1, (int)(imy * (float)FB))], 1u);
        atomicAdd(&s_fh[min(FB - 1, (int)(imz * (float)FB))], 1u);
        atomicAdd(&s_fh[min(FB - 1, (int)(imw * (float)FB))], 1u);

        int gx = grayi(q8(b0.x), q8(b1.x), q8(b2.x));
        int gy = grayi(q8(b0.y), q8(b1.y), q8(b2.y));
        int gz = grayi(q8(b0.z), q8(b1.z), q8(b2.z));
        int gw = grayi(q8(b0.w), q8(b1.w), q8(b2.w));

        int dgx = abs(gx - gPx), dgy = abs(gy - gPy);
        int dgz = abs(gz - gPz), dgw = abs(gw - gPw);
        sRsI += dgx + dgy + dgz + dgw + 2 * (gx + gy + gz + gw);

        sIs += fabsf(lv.x - lP.x) * s_lut[dgx] + 2.0f * fabsf(lv.x) * s_lut[gx]
             + fabsf(lv.y - lP.y) * s_lut[dgy] + 2.0f * fabsf(lv.y) * s_lut[gy]
             + fabsf(lv.z - lP.z) * s_lut[dgz] + 2.0f * fabsf(lv.z) * s_lut[gz]
             + fabsf(lv.w - lP.w) * s_lut[dgw] + 2.0f * fabsf(lv.w) * s_lut[gw];

        gPx = gx; gPy = gy; gPz = gz; gPw = gw;
        lP = lv;
    };

    #pragma unroll 1
    for (int rr = 0; rr < nr - 1; rr++) {
        int nidx = idx + W4;
        float4 na0 = __ldcs(&in[nidx]), na1 = __ldcs(&in[nidx + HW4]), na2 = __ldcs(&in[nidx + 2 * HW4]);
        float4 nb0 = __ldcs(&Rp[nidx]), nb1 = __ldcs(&Rp[nidx + HW4]), nb2 = __ldcs(&Rp[nidx + 2 * HW4]);
        float4 nlv = __ldcs(&Lp[nidx]);
        body(rr);
        a0 = na0; a1 = na1; a2 = na2;
        b0 = nb0; b1 = nb1; b2 = nb2;
        lv = nlv;
        idx = nidx;
    }
    body(nr - 1);

    if (r0 + nr == HH) {   // bottom padded edge
        sRsI += gPx + gPy + gPz + gPw;
        sIs  += fabsf(lP.x) * s_lut[gPx] + fabsf(lP.y) * s_lut[gPy]
              + fabsf(lP.z) * s_lut[gPz] + fabsf(lP.w) * s_lut[gPw];
    }

    __syncthreads();   // fine hist complete for this CTA
    // flush fine hist to global (distinct addresses -> REDG-friendly)
    for (int i = tid; i < FB; i += NTHR) {
        unsigned c = s_fh[i];
        if (c) atomicAdd(&g_fhist[i], c);
    }

    // block reduce (16 warps)
    double dRec = (double)sRec, dIs = (double)sIs;
    int    iRs = sRsI;
    const unsigned m = 0xffffffffu;
    for (int o = 16; o; o >>= 1) {
        dRec += __shfl_down_sync(m, dRec, o);
        dIs  += __shfl_down_sync(m, dIs,  o);
        iRs  += __shfl_down_sync(m, iRs,  o);
        vmin = fminf(vmin, __shfl_down_sync(m, vmin, o));
        vmax = fmaxf(vmax, __shfl_down_sync(m, vmax, o));
    }
    int lane = tid & 31, wid = tid >> 5;
    if (lane == 0) {
        redd[0][wid] = dRec; redd[1][wid] = (double)iRs; redd[2][wid] = dIs;
        redf[0][wid] = vmin; redf[1][wid] = vmax;
    }
    __syncthreads();
    if (wid == 0) {
        double dRs;
        dRec = (lane < 16) ? redd[0][lane] : 0.0;
        dRs  = (lane < 16) ? redd[1][lane] : 0.0;
        dIs  = (lane < 16) ? redd[2][lane] : 0.0;
        vmin = (lane < 16) ? redf[0][lane] : 3.0f;
        vmax = (lane < 16) ? redf[1][lane] : -1.0f;
        for (int o = 8; o; o >>= 1) {
            dRec += __shfl_down_sync(m, dRec, o);
            dRs  += __shfl_down_sync(m, dRs,  o);
            dIs  += __shfl_down_sync(m, dIs,  o);
            vmin = fminf(vmin, __shfl_down_sync(m, vmin, o));
            vmax = fmaxf(vmax, __shfl_down_sync(m, vmax, o));
        }
        if (lane == 0) {
            atomicAdd(&g_sums[0], dRec);
            atomicAdd(&g_sums[1], dRs);
            atomicAdd(&g_sums[2], dIs);
            atomicMin(&g_minbits, __float_as_int(vmin));
            atomicMax(&g_maxbits, __float_as_int(vmax));
        }
    }

    gridbar(NCTA);

    // ---------------- Phase 3: rebin + cdf + interp + eq-sum ----------------
    const float gmin = __int_as_float(__ldcg(&g_minbits));
    const float gmax = __int_as_float(__ldcg(&g_maxbits));
    const float scale = 256.0f / (gmax - gmin);

    if (tid < 256) s_ch[tid] = 0u;
    __syncthreads();
    for (int f = tid; f < FB; f += NTHR) {
        unsigned c = __ldcg(&g_fhist[f]);
        if (c) {
            float center = ((float)f + 0.5f) * (1.0f / (float)FB);
            int k = min(255, max(0, (int)((center - gmin) * scale)));
            atomicAdd(&s_ch[k], c);
        }
    }
    __syncthreads();

    if (tid < 256) s_cdf[tid] = (float)s_ch[tid];   // total 2^22: exact in fp32
    __syncthreads();
    for (int off = 1; off < 256; off <<= 1) {
        float t = 0.0f;
        if (tid < 256 && tid >= off) t = s_cdf[tid - off];
        __syncthreads();
        if (tid < 256) s_cdf[tid] += t;
        __syncthreads();
    }
    float norm = s_cdf[255];
    __syncthreads();
    if (tid < 256) s_cdf[tid] = s_cdf[tid] / norm;
    __syncthreads();
    if (tid < 256) {   // cdfp pairs overwrite the fine-hist smem (no longer needed)
        float c0 = s_cdf[tid];
        float c1 = (tid < 255) ? s_cdf[tid + 1] : c0;
        s_cdfp[tid] = make_float2(c0, c1);
    }
    __syncthreads();

    const int nelem = nr * 512;
    float sEq = 0.f;
    for (int i = tid; i < nelem; i += NTHR) {
        uint2 u = s_im[i];
        uint2 ru = s_rm[i];
        float2 v0 = unpackh2(u.x), v1 = unpackh2(u.y);
        float2 r0f = unpackh2(ru.x), r1f = unpackh2(ru.y);
        sEq += fabsf(r0f.x - interp1p(v0.x, gmin, scale, s_cdfp))
             + fabsf(r0f.y - interp1p(v0.y, gmin, scale, s_cdfp))
             + fabsf(r1f.x - interp1p(v1.x, gmin, scale, s_cdfp))
             + fabsf(r1f.y - interp1p(v1.y, gmin, scale, s_cdfp));
    }
    double dEq = (double)sEq;
    for (int o = 16; o; o >>= 1) dEq += __shfl_down_sync(m, dEq, o);
    if (lane == 0) redd[0][wid] = dEq;
    __syncthreads();
    if (wid == 0) {
        dEq = (lane < 16) ? redd[0][lane] : 0.0;
        for (int o = 8; o; o >>= 1) dEq += __shfl_down_sync(m, dEq, o);
        if (lane == 0) atomicAdd(&g_sums[3], dEq);
    }

    gridbar(2 * NCTA);

    // ---------------- Final combine ----------------
    if (cta == 0 && tid == 0) {
        double recon = __ldcg(&g_sums[0]) / (3.0 * (double)HWN);
        double denom = 2.0 * (double)(HH + 1) * (double)(WW + 2);
        double rs = __ldcg(&g_sums[1]) / (255.0 * denom);
        double is = __ldcg(&g_sums[2]) / denom;
        double eq = __ldcg(&g_sums[3]) / (double)HWN;
        out[0] = (float)(recon + 0.1 * is + 0.1 * eq + 0.01 * rs);
    }
}

extern "C" void kernel_launch(void* const* d_in, const int* in_sizes, int n_in,
                              void* d_out, int out_size) {
    const float4* in = (const float4*)d_in[0];
    const float4* Rp = (const float4*)d_in[1];
    const float4* Lp = (const float4*)d_in[2];
    (void)in_sizes; (void)n_in; (void)out_size;

    cudaFuncSetAttribute(kmain, cudaFuncAttributeMaxDynamicSharedMemorySize, SMEM_BYTES);

    k_zero<<<1, 256>>>();
    kmain<<<NCTA, NTHR, SMEM_BYTES>>>(in, Rp, Lp, (float*)d_out);
}